// round 3
// baseline (speedup 1.0000x reference)
#include <cuda_runtime.h>
#include <math.h>

// Problem constants
#define N_ROWS   16384
#define NCLS     1000
#define N_ITER   80
// Bracket width <= ~3; after ~24 halvings lo/hi are adjacent fp32 values and
// mid is bitwise-fixed, so 36 iterations === reference's 50.
#define N_BISECT 36
#define WPB      8          // warps (rows) per block
#define FULLJ    31         // j=0..30 cover elems 0..991
#define TAILCNT  (NCLS - FULLJ*32)  // 8 lanes own a 32nd element

__device__ float g_row_loss[N_ROWS];

__global__ __launch_bounds__(32*WPB)
void pgd_kernel(const float* __restrict__ x, const int* __restrict__ y)
{
    const int warp = threadIdx.x >> 5;
    const int lane = threadIdx.x & 31;
    const int row  = blockIdx.x * WPB + warp;

    const float* __restrict__ xr = x + (size_t)row * NCLS;
    const bool tail = lane < TAILCNT;

    // ---- load row (coalesced, lane-strided: elem = j*32 + lane) ----
    float c[32];
#pragma unroll
    for (int j = 0; j < FULLJ; ++j) c[j] = xr[j*32 + lane];
    c[FULLJ] = tail ? xr[FULLJ*32 + lane] : 0.0f;

    // ---- L2 normalize (norm clamped at 1e-12) ----
    float ss = 0.0f;
#pragma unroll
    for (int j = 0; j < 32; ++j) ss = fmaf(c[j], c[j], ss);
#pragma unroll
    for (int o = 16; o; o >>= 1) ss += __shfl_xor_sync(0xffffffffu, ss, o);
    const float norm = fmaxf(sqrtf(ss), 1e-12f);
#pragma unroll
    for (int j = 0; j < 32; ++j) c[j] = __fdiv_rn(c[j], norm);

    // p held implicitly as sat(v - nu); init p = k/n = 0.005
    float v[32];
    float nu = 0.0f;
#pragma unroll
    for (int j = 0; j < 32; ++j) v[j] = 0.005f;

    const float PC_LO = 1e-6f;
    const float PC_HI = 1.0f - 1e-6f;

    for (int it = 0; it < N_ITER; ++it) {
        // ---- gradient step: v = p + alpha*(c + log1p(-pc) - log(pc)) ----
        float vmin =  1e30f;
        float vmax = -1e30f;
#pragma unroll
        for (int j = 0; j < 32; ++j) {
            if (j < FULLJ || tail) {
                float p    = __saturatef(v[j] - nu);
                float pc   = fminf(fmaxf(p, PC_LO), PC_HI);
                float grad = c[j] + log1pf(-pc) - logf(pc);
                float nv   = fmaf(0.025f, grad, p);
                v[j] = nv;
                vmin = fminf(vmin, nv);
                vmax = fmaxf(vmax, nv);
            }
        }
#pragma unroll
        for (int o = 16; o; o >>= 1) {
            vmin = fminf(vmin, __shfl_xor_sync(0xffffffffu, vmin, o));
            vmax = fmaxf(vmax, __shfl_xor_sync(0xffffffffu, vmax, o));
        }

        // ---- capped-simplex projection: bisection on the shift nu ----
        float lo = vmin - 1.0f;
        float hi = vmax;
        for (int b = 0; b < N_BISECT; ++b) {
            const float mid = 0.5f * (lo + hi);
            float s0 = 0.f, s1 = 0.f, s2 = 0.f, s3 = 0.f;
#pragma unroll
            for (int j = 0; j < 28; j += 4) {
                s0 += __saturatef(v[j+0] - mid);
                s1 += __saturatef(v[j+1] - mid);
                s2 += __saturatef(v[j+2] - mid);
                s3 += __saturatef(v[j+3] - mid);
            }
            s0 += __saturatef(v[28] - mid);
            s1 += __saturatef(v[29] - mid);
            s2 += __saturatef(v[30] - mid);
            if (tail) s3 += __saturatef(v[31] - mid);
            float s = (s0 + s1) + (s2 + s3);
#pragma unroll
            for (int o = 16; o; o >>= 1) s += __shfl_xor_sync(0xffffffffu, s, o);
            const bool big = s > 5.0f;
            lo = big ? mid : lo;
            hi = big ? hi  : mid;
        }
        nu = 0.5f * (lo + hi);
    }

    // ---- p_y = clip(v[y] - nu, 0, 1); loss = -log(p_y + 1e-8) ----
    const int yi = y[row];                         // int32 labels!
    float py = 0.0f;
#pragma unroll
    for (int j = 0; j < 32; ++j) {
        if (j*32 + lane == yi) py = __saturatef(v[j] - nu);
    }
#pragma unroll
    for (int o = 16; o; o >>= 1) py += __shfl_xor_sync(0xffffffffu, py, o);

    if (lane == 0) g_row_loss[row] = -logf(py + 1e-8f);
}

__global__ void reduce_kernel(float* __restrict__ out)
{
    __shared__ float sh[8];
    float s = 0.0f;
    for (int i = threadIdx.x; i < N_ROWS; i += 256) s += g_row_loss[i];
#pragma unroll
    for (int o = 16; o; o >>= 1) s += __shfl_xor_sync(0xffffffffu, s, o);
    const int w = threadIdx.x >> 5;
    const int l = threadIdx.x & 31;
    if (l == 0) sh[w] = s;
    __syncthreads();
    if (threadIdx.x == 0) {
        float t = 0.0f;
#pragma unroll
        for (int i = 0; i < 8; ++i) t += sh[i];
        out[0] = t * (1.0f / (float)N_ROWS);
    }
}

extern "C" void kernel_launch(void* const* d_in, const int* in_sizes, int n_in,
                              void* d_out, int out_size)
{
    const float* x = (const float*)d_in[0];
    const int*   y = (const int*)d_in[1];
    pgd_kernel<<<N_ROWS / WPB, 32 * WPB>>>(x, y);
    reduce_kernel<<<1, 256>>>((float*)d_out);
}

// round 5
// speedup vs baseline: 2.0195x; 2.0195x over previous
#include <cuda_runtime.h>
#include <math.h>

// Problem constants
#define N_ROWS   16384
#define NCLS     1000
#define N_ITER   80
// Bracket width <= 2.75; 2.75*2^-30 = 2.6e-9 < ulp(0.34) = 3e-8, so nu matches
// the reference's 50-iteration bisection to <= 1 ulp.
#define N_BISECT 30
#define WPB      8          // warps (rows) per block
#define FULLJ    31         // j=0..30 cover elems 0..991
#define TAILCNT  (NCLS - FULLJ*32)  // 8 lanes own a 32nd element

__device__ float g_row_loss[N_ROWS];

__global__ __launch_bounds__(32*WPB)
void pgd_kernel(const float* __restrict__ x, const int* __restrict__ y)
{
    const int warp = threadIdx.x >> 5;
    const int lane = threadIdx.x & 31;
    const int row  = blockIdx.x * WPB + warp;

    const float* __restrict__ xr = x + (size_t)row * NCLS;
    const bool tail = lane < TAILCNT;

    // ---- load row (coalesced: elem = j*32 + lane) ----
    float c[32];
#pragma unroll
    for (int j = 0; j < FULLJ; ++j) c[j] = xr[j*32 + lane];
    c[FULLJ] = tail ? xr[FULLJ*32 + lane] : 0.0f;

    // ---- L2 normalize, folding alpha: c <- alpha * x / norm ----
    float ss = 0.0f;
#pragma unroll
    for (int j = 0; j < 32; ++j) ss = fmaf(c[j], c[j], ss);
#pragma unroll
    for (int o = 16; o; o >>= 1) ss += __shfl_xor_sync(0xffffffffu, ss, o);
    const float scl = __fdiv_rn(0.025f, fmaxf(sqrtf(ss), 1e-12f));
#pragma unroll
    for (int j = 0; j < 32; ++j) c[j] *= scl;

    // p is held implicitly as sat(v - nu); init p = k/n = 0.005
    float v[32];
    float nu = 0.0f;
#pragma unroll
    for (int j = 0; j < 32; ++j) v[j] = 0.005f;

    const float PC_LO = 1e-6f;
    const float PC_HI = 1.0f - 1e-6f;
    const float C1    = 0.025f * 0.69314718055994531f;   // alpha * ln2

    for (int it = 0; it < N_ITER; ++it) {
        // ---- gradient step: v = p + alpha*c + alpha*ln2*(lg2(1-pc) - lg2(pc)) ----
        // The pc clamp makes this formula also produce the correct boundary
        // values (+-alpha*13.8155 + alpha*c) for clipped coordinates.
        float vmin =  1e30f;
        float vmax = -1e30f;
#pragma unroll
        for (int j = 0; j < 32; ++j) {
            if (j < FULLJ || tail) {
                float p  = __saturatef(v[j] - nu);
                float pc = fminf(fmaxf(p, PC_LO), PC_HI);
                float d  = __log2f(1.0f - pc) - __log2f(pc);
                float nv = fmaf(C1, d, p + c[j]);
                v[j] = nv;
                vmin = fminf(vmin, nv);
                vmax = fmaxf(vmax, nv);
            }
        }
#pragma unroll
        for (int o = 16; o; o >>= 1) {
            vmin = fminf(vmin, __shfl_xor_sync(0xffffffffu, vmin, o));
            vmax = fmaxf(vmax, __shfl_xor_sync(0xffffffffu, vmax, o));
        }

        // ---- capped-simplex projection: bisection on the shift nu (exact) ----
        float lo = vmin - 1.0f;
        float hi = vmax;
        for (int b = 0; b < N_BISECT; ++b) {
            const float mid = 0.5f * (lo + hi);
            float s0 = 0.f, s1 = 0.f, s2 = 0.f, s3 = 0.f;
#pragma unroll
            for (int j = 0; j < 28; j += 4) {
                s0 += __saturatef(v[j+0] - mid);
                s1 += __saturatef(v[j+1] - mid);
                s2 += __saturatef(v[j+2] - mid);
                s3 += __saturatef(v[j+3] - mid);
            }
            s0 += __saturatef(v[28] - mid);
            s1 += __saturatef(v[29] - mid);
            s2 += __saturatef(v[30] - mid);
            if (tail) s3 += __saturatef(v[31] - mid);
            float s = (s0 + s1) + (s2 + s3);
#pragma unroll
            for (int o = 16; o; o >>= 1) s += __shfl_xor_sync(0xffffffffu, s, o);
            const bool big = s > 5.0f;
            lo = big ? mid : lo;
            hi = big ? hi  : mid;
        }
        nu = 0.5f * (lo + hi);
    }

    // ---- p_y = clip(v[y] - nu, 0, 1); loss = -log(p_y + 1e-8) ----
    const int yi = y[row];
    float py = 0.0f;
#pragma unroll
    for (int j = 0; j < 32; ++j) {
        if (j*32 + lane == yi) py = __saturatef(v[j] - nu);
    }
#pragma unroll
    for (int o = 16; o; o >>= 1) py += __shfl_xor_sync(0xffffffffu, py, o);

    if (lane == 0) g_row_loss[row] = -logf(py + 1e-8f);
}

__global__ void reduce_kernel(float* __restrict__ out)
{
    __shared__ float sh[8];
    float s = 0.0f;
    for (int i = threadIdx.x; i < N_ROWS; i += 256) s += g_row_loss[i];
#pragma unroll
    for (int o = 16; o; o >>= 1) s += __shfl_xor_sync(0xffffffffu, s, o);
    const int w = threadIdx.x >> 5;
    const int l = threadIdx.x & 31;
    if (l == 0) sh[w] = s;
    __syncthreads();
    if (threadIdx.x == 0) {
        float t = 0.0f;
#pragma unroll
        for (int i = 0; i < 8; ++i) t += sh[i];
        out[0] = t * (1.0f / (float)N_ROWS);
    }
}

extern "C" void kernel_launch(void* const* d_in, const int* in_sizes, int n_in,
                              void* d_out, int out_size)
{
    const float* x = (const float*)d_in[0];
    const int*   y = (const int*)d_in[1];
    pgd_kernel<<<N_ROWS / WPB, 32 * WPB>>>(x, y);
    reduce_kernel<<<1, 256>>>((float*)d_out);
}